// round 15
// baseline (speedup 1.0000x reference)
#include <cuda_runtime.h>

#define B_   8
#define C_   8
#define H_   512
#define W_   1024
#define HW_  (H_*W_)
#define NPIX (B_*HW_)

#define GXB  37                   // bands per image (13-14 rows each)
#define NBLK (GXB * B_)           // 296 = 2 CTAs x 148 SMs -> exactly one wave
#define TP   258                  // mask tile pitch (1 zero halo u32 each side)
#define LN2F 0.69314718055994531f
#define L2EF 1.4426950408889634f

typedef unsigned long long ull;

// ---------------- device scratch (no allocations allowed) ----------------
// per-block partial sums, written unconditionally (no zeroing, no atomics)
// rows: 0..63 probsum(b*8+c), 64..127 inter(b*8+c), 128..135 ce(b) [lg2 units],
//       136..143 cb(b) [lg2 units], 144..207 cnt(b*8+c)
__device__ float g_lp[208 * NBLK];
__device__ unsigned int g_ctr = 0;

__device__ __forceinline__ float wredf(float v) {
    #pragma unroll
    for (int o = 16; o; o >>= 1) v += __shfl_xor_sync(0xffffffffu, v, o);
    return v;
}
__device__ __forceinline__ float lg2f(float x) {
    float r; asm("lg2.approx.f32 %0, %1;" : "=f"(r) : "f"(x)); return r;
}
__device__ __forceinline__ float ex2f_(float x) {
    float r; asm("ex2.approx.f32 %0, %1;" : "=f"(r) : "f"(x)); return r;
}
__device__ __forceinline__ float rcpf_(float x) {
    float r; asm("rcp.approx.f32 %0, %1;" : "=f"(r) : "f"(x)); return r;
}
__device__ __forceinline__ ull mul2(ull a, ull b) {
    ull r; asm("mul.rn.f32x2 %0, %1, %2;" : "=l"(r) : "l"(a), "l"(b)); return r;
}
__device__ __forceinline__ ull add2(ull a, ull b) {
    ull r; asm("add.rn.f32x2 %0, %1, %2;" : "=l"(r) : "l"(a), "l"(b)); return r;
}
__device__ __forceinline__ ull fma2_(ull a, ull b, ull c) {
    ull r; asm("fma.rn.f32x2 %0, %1, %2, %3;" : "=l"(r) : "l"(a), "l"(b), "l"(c)); return r;
}
__device__ __forceinline__ ull pk2(float lo, float hi) {
    ull r; asm("mov.b64 %0, {%1, %2};" : "=l"(r) : "f"(lo), "f"(hi)); return r;
}
__device__ __forceinline__ void up2(ull v, float& lo, float& hi) {
    asm("mov.b64 {%0, %1}, %2;" : "=f"(lo), "=f"(hi) : "l"(v));
}

// ---------------- single fused kernel ----------------
__global__ __launch_bounds__(256, 2)
void fused_kernel(const float* __restrict__ pred, const int* __restrict__ tgt,
                  float* __restrict__ out) {
    const int b   = blockIdx.y;
    const int kb  = blockIdx.x;
    const int bid = b * GXB + kb;
    const int tid = threadIdx.x;
    const int r0  = (kb * H_) / GXB;
    const int r1  = ((kb + 1) * H_) / GXB;   // rows = r1-r0 in {13,14}
    const int rows = r1 - r0;

    const float* predb = pred + (size_t)b * (C_ * HW_);
    const int*   tgtb  = tgt  + (size_t)b * HW_;

    __shared__ unsigned mtile[18 * TP];    // one-hot mask rows; reused as dice bins
    __shared__ unsigned ctile[14 * 256];   // per-px byte: class(3b) | bnd<<3
    __shared__ float    sred[8][26];
    __shared__ float    S[208];
    __shared__ float    dpart[2];
    __shared__ unsigned s_ticket;

    // zero halo columns for all 18 mask rows
    if (tid < 36) mtile[(tid >> 1) * TP + ((tid & 1) ? TP - 1 : 0)] = 0u;

    // ===== phase 1: mask rows r0-2 .. r0+15 (OOB rows = 0 = skipped tap) =====
    ull hist = 0ull;                       // byte-packed class counters (<=56/class)
    #pragma unroll
    for (int i = 0; i < 18; i++) {
        const int g = r0 - 2 + i;
        unsigned mrow = 0u;
        if (g >= 0 && g < H_) {
            const int4 v = *(const int4*)(tgtb + g * W_ + tid * 4);
            const unsigned m0 = 1u << v.x, m1 = 1u << v.y, m2 = 1u << v.z, m3 = 1u << v.w;
            mrow = __byte_perm(__byte_perm(m0, m1, 0x0040),
                               __byte_perm(m2, m3, 0x0040), 0x5410);
            if (i >= 2 && i < 16) {
                ctile[(i - 2) * 256 + tid] =
                    __byte_perm(__byte_perm(v.x, v.y, 0x0040),
                                __byte_perm(v.z, v.w, 0x0040), 0x5410);
                if (g < r1) {              // class histogram off the hot loop
                    hist += (1ull << (v.x << 3)) + (1ull << (v.y << 3))
                          + (1ull << (v.z << 3)) + (1ull << (v.w << 3));
                }
            }
        }
        mtile[i * TP + 1 + tid] = mrow;
    }
    __syncthreads();

    // 5-wide row-OR window of mask row i (rolling, each computed once)
    #define WIN(i, dst) { \
        const unsigned* row_ = &mtile[(i) * TP]; \
        const unsigned L_ = row_[tid], Cm_ = row_[tid + 1], R_ = row_[tid + 2]; \
        const unsigned a_ = __byte_perm(L_, Cm_, 0x5432); \
        const unsigned b2_ = __byte_perm(L_, Cm_, 0x6543); \
        const unsigned c_ = __byte_perm(Cm_, R_, 0x4321); \
        const unsigned d_ = __byte_perm(Cm_, R_, 0x5432); \
        dst = (a_ | b2_) | Cm_ | (c_ | d_); \
    }

    {
        unsigned w0, w1;
        WIN(1, w0); WIN(2, w1);
        #pragma unroll
        for (int rr = 0; rr < 14; rr++) {
            unsigned w2; WIN(rr + 3, w2);
            const unsigned m = w0 | w1 | w2
                             | mtile[rr * TP + 1 + tid]
                             | mtile[(rr + 4) * TP + 1 + tid];
            const unsigned t2 = m & (m - 0x01010101u);  // center bit set -> no borrow
            const unsigned y  = (((t2 & 0x7f7f7f7fu) + 0x7f7f7f7fu) | t2);
            ctile[rr * 256 + tid] |= ((y >> 7) & 0x01010101u) << 3;
            w0 = w1; w1 = w2;
        }
    }
    __syncthreads();   // all mask reads done -> reuse mtile as dice bins

    float* inter_s = (float*)mtile;        // 8*256 bins, own-column only (no races)
    #pragma unroll
    for (int c = 0; c < 8; c++) inter_s[c * 256 + tid] = 0.f;

    // ===== phase 2: 14 steps, one full row each, 4 px/thread (LDG.128) =====
    ull ps2[8];                            // packed probsum accumulators
    #pragma unroll
    for (int c = 0; c < 8; c++) ps2[c] = 0ull;
    float ce_s = 0.f, cb_s = 0.f;          // lg2 units
    const ull L2E2 = pk2(L2EF, L2EF);

    // step st = image row r0+st; 13-row bands' step 13 reads the next band's
    // first row (in-image for all bands; last band has 14 rows), weight 0.
    const float* pb = predb + (size_t)r0 * W_ + tid * 4;

    #pragma unroll
    for (int st = 0; st < 14; st++) {
        float4 v4[8];
        #pragma unroll
        for (int c = 0; c < 8; c++) v4[c] = __ldcs((const float4*)(pb + c * HW_));
        pb += W_;

        const bool valid = st < rows;      // uniform per CTA
        const unsigned cw = ctile[st * 256 + tid];

        #pragma unroll
        for (int h = 0; h < 2; h++) {      // px pair (0,1) then (2,3)
            float el[8], eh[8];
            ull e2[8];
            ull sa = 0ull, sb = 0ull;
            #pragma unroll
            for (int c = 0; c < 8; c++) {
                const ull nb = h ? pk2(v4[c].z, v4[c].w) : pk2(v4[c].x, v4[c].y);
                const ull x = mul2(nb, L2E2);
                float xl, xh; up2(x, xl, xh);
                el[c] = ex2f_(xl); eh[c] = ex2f_(xh);
                e2[c] = pk2(el[c], eh[c]);
                if (c & 1) sb = add2(sb, e2[c]); else sa = add2(sa, e2[c]);
            }
            float sl, sh; up2(add2(sa, sb), sl, sh);

            const float invl = rcpf_(sl), invh = rcpf_(sh);
            const float invlw = valid ? invl : 0.f;
            const float invhw = valid ? invh : 0.f;
            const ull inv2w = pk2(invlw, invhw);

            #pragma unroll
            for (int c = 0; c < 8; c++) ps2[c] = fma2_(e2[c], inv2w, ps2[c]);

            const unsigned cwh = cw >> (16 * h);
            const int tl = cwh & 7, th = (cwh >> 8) & 7;

            float etl = el[0], eth = eh[0];
            #pragma unroll
            for (int c = 1; c < 8; c++) {
                etl = (tl == c) ? el[c] : etl;
                eth = (th == c) ? eh[c] : eth;
            }

            inter_s[tl * 256 + tid] += etl * invlw;   // conflict-free: bank = tid%32
            inter_s[th * 256 + tid] += eth * invhw;

            const float cel = lg2f(etl * invl);       // log2 p_t
            const float ceh = lg2f(eth * invh);
            ce_s -= valid ? (cel + ceh) : 0.f;
            cb_s -= ((cwh & 8u)    && valid) ? cel : 0.f;
            cb_s -= ((cwh & 0x800u)&& valid) ? ceh : 0.f;
        }
    }

    float probsum[8], inter[8];
    #pragma unroll
    for (int c = 0; c < 8; c++) {
        float a, z; up2(ps2[c], a, z);
        probsum[c] = a + z;
        inter[c] = inter_s[c * 256 + tid];
    }

    // ============ block reduction -> per-block slots ============
    #pragma unroll
    for (int c = 0; c < 8; c++) { probsum[c] = wredf(probsum[c]); inter[c] = wredf(inter[c]); }
    ce_s = wredf(ce_s);
    cb_s = wredf(cb_s);
    float cntf[8];
    #pragma unroll
    for (int c = 0; c < 8; c++) cntf[c] = wredf((float)(int)((hist >> (c * 8)) & 0xffull));

    const int wid = tid >> 5, lane = tid & 31;
    if (lane == 0) {
        #pragma unroll
        for (int c = 0; c < 8; c++) {
            sred[wid][c]      = probsum[c];
            sred[wid][8 + c]  = inter[c];
            sred[wid][18 + c] = cntf[c];
        }
        sred[wid][16] = ce_s; sred[wid][17] = cb_s;
    }
    __syncthreads();
    if (tid < 26) {
        float s = 0.f;
        #pragma unroll
        for (int w = 0; w < 8; w++) s += sred[w][tid];
        const int i = tid;
        int row;
        if      (i < 8)   row = b * 8 + i;            // probsum
        else if (i < 16)  row = 64 + b * 8 + (i - 8); // inter
        else if (i == 16) row = 128 + b;              // ce (lg2)
        else if (i == 17) row = 136 + b;              // cb (lg2)
        else              row = 144 + b * 8 + (i-18); // cnt
        g_lp[row * NBLK + bid] = s;
    }

    // ============ last block finalizes ============
    __threadfence();
    __syncthreads();
    if (tid == 0) s_ticket = atomicAdd(&g_ctr, 1u);
    __syncthreads();
    if (s_ticket != NBLK - 1) return;

    if (tid < 208) {
        const float4* rp = (const float4*)&g_lp[tid * NBLK];
        float s = 0.f;
        #pragma unroll 4
        for (int x = 0; x < NBLK / 4; x++) {
            const float4 v = rp[x];
            s += (v.x + v.y) + (v.z + v.w);
        }
        S[tid] = s;
    }
    __syncthreads();

    if (tid < 64) {
        float term = (2.f * S[64 + tid] + 1e-6f) / (S[tid] + S[144 + tid] + 1e-6f);
        term = wredf(term);
        if ((tid & 31) == 0) dpart[tid >> 5] = term;
    }
    __syncthreads();
    if (tid == 0) {
        float ce = 0.f, cb = 0.f;
        #pragma unroll
        for (int k = 0; k < 8; k++) { ce += S[128 + k]; cb += S[136 + k]; }
        ce *= LN2F; cb *= LN2F;                          // lg2 -> ln
        const float invN = 1.f / (float)NPIX;
        const float ce_m = ce * invN;
        const float bd   = (ce + 9.f * cb) * invN;       // wmap: 10 on boundary, 1 else
        const float dice = 1.f - (dpart[0] + dpart[1]) * (1.f / 64.f);
        out[0] = 1.f * ce_m + 3.f * dice + 2.f * bd;
        g_ctr = 0;   // reset for next graph replay (deterministic)
    }
}

// ---------------- launch ----------------
extern "C" void kernel_launch(void* const* d_in, const int* in_sizes, int n_in,
                              void* d_out, int out_size) {
    (void)n_in; (void)out_size;
    const float* pred;
    const int*   tgt;
    if (in_sizes[0] == B_ * C_ * HW_) {
        pred = (const float*)d_in[0];
        tgt  = (const int*)d_in[1];
    } else {
        pred = (const float*)d_in[1];
        tgt  = (const int*)d_in[0];
    }
    fused_kernel<<<dim3(GXB, B_), 256>>>(pred, tgt, (float*)d_out);
}

// round 16
// speedup vs baseline: 1.0374x; 1.0374x over previous
#include <cuda_runtime.h>

#define B_   8
#define C_   8
#define H_   512
#define W_   1024
#define HW_  (H_*W_)
#define NPIX (B_*HW_)

#define GXB  64                   // bands per image, 8 rows each (uniform)
#define NBLK (GXB * B_)           // 512 blocks -> single wave at 4 CTA/SM
#define TP   258                  // mask tile pitch (1 zero halo u32 each side)
#define LN2F 0.69314718055994531f
#define L2EF 1.4426950408889634f

typedef unsigned long long ull;

// ---------------- device scratch (no allocations allowed) ----------------
// per-block partial sums, written unconditionally (no zeroing, no atomics)
// rows: 0..63 probsum(b*8+c), 64..127 inter(b*8+c), 128..135 ce(b) [lg2 units],
//       136..143 cb(b) [lg2 units], 144..207 cnt(b*8+c)
__device__ float g_lp[208 * NBLK];
__device__ unsigned int g_ctr = 0;

__device__ __forceinline__ float wredf(float v) {
    #pragma unroll
    for (int o = 16; o; o >>= 1) v += __shfl_xor_sync(0xffffffffu, v, o);
    return v;
}
__device__ __forceinline__ float lg2f(float x) {
    float r; asm("lg2.approx.f32 %0, %1;" : "=f"(r) : "f"(x)); return r;
}
__device__ __forceinline__ float ex2f_(float x) {
    float r; asm("ex2.approx.f32 %0, %1;" : "=f"(r) : "f"(x)); return r;
}
__device__ __forceinline__ float rcpf_(float x) {
    float r; asm("rcp.approx.f32 %0, %1;" : "=f"(r) : "f"(x)); return r;
}
__device__ __forceinline__ ull mul2(ull a, ull b) {
    ull r; asm("mul.rn.f32x2 %0, %1, %2;" : "=l"(r) : "l"(a), "l"(b)); return r;
}
__device__ __forceinline__ ull add2(ull a, ull b) {
    ull r; asm("add.rn.f32x2 %0, %1, %2;" : "=l"(r) : "l"(a), "l"(b)); return r;
}
__device__ __forceinline__ ull fma2_(ull a, ull b, ull c) {
    ull r; asm("fma.rn.f32x2 %0, %1, %2, %3;" : "=l"(r) : "l"(a), "l"(b), "l"(c)); return r;
}
__device__ __forceinline__ ull pk2(float lo, float hi) {
    ull r; asm("mov.b64 %0, {%1, %2};" : "=l"(r) : "f"(lo), "f"(hi)); return r;
}
__device__ __forceinline__ void up2(ull v, float& lo, float& hi) {
    asm("mov.b64 {%0, %1}, %2;" : "=f"(lo), "=f"(hi) : "l"(v));
}

// ---------------- single fused kernel ----------------
__global__ __launch_bounds__(256, 4)
void fused_kernel(const float* __restrict__ pred, const int* __restrict__ tgt,
                  float* __restrict__ out) {
    const int b   = blockIdx.y;
    const int kb  = blockIdx.x;
    const int bid = b * GXB + kb;
    const int tid = threadIdx.x;
    const int r0  = kb * 8;                // 8 rows per band, uniform

    const float* predb = pred + (size_t)b * (C_ * HW_);
    const int*   tgtb  = tgt  + (size_t)b * HW_;

    __shared__ unsigned mtile[12 * TP];    // one-hot mask rows; reused as dice bins
    __shared__ unsigned ctile[8 * 256];    // per-px byte: class(3b) | bnd<<3
    __shared__ float    sred[8][26];
    __shared__ float    S[208];
    __shared__ float    dpart[2];
    __shared__ unsigned s_ticket;

    // ---- issue step-0 pred loads FIRST: they age in flight during phase 1 ----
    const float* pb = predb + (size_t)r0 * W_ + tid * 2;
    ull nb2[8];
    #pragma unroll
    for (int c = 0; c < 8; c++) nb2[c] = __ldcs((const ull*)(pb + c * HW_));

    // zero halo columns for all 12 mask rows
    if (tid < 24) mtile[(tid >> 1) * TP + ((tid & 1) ? TP - 1 : 0)] = 0u;

    // ===== phase 1: mask rows r0-2 .. r0+9 (OOB rows = 0 = skipped tap) =====
    ull hist = 0ull;                       // byte-packed class counters (<=32/class)
    #pragma unroll
    for (int i = 0; i < 12; i++) {
        const int g = r0 - 2 + i;
        unsigned mrow = 0u;
        if (g >= 0 && g < H_) {
            const int4 v = *(const int4*)(tgtb + g * W_ + tid * 4);
            const unsigned m0 = 1u << v.x, m1 = 1u << v.y, m2 = 1u << v.z, m3 = 1u << v.w;
            mrow = __byte_perm(__byte_perm(m0, m1, 0x0040),
                               __byte_perm(m2, m3, 0x0040), 0x5410);
            if (i >= 2 && i < 10) {        // center rows: always fully valid
                ctile[(i - 2) * 256 + tid] =
                    __byte_perm(__byte_perm(v.x, v.y, 0x0040),
                                __byte_perm(v.z, v.w, 0x0040), 0x5410);
                hist += (1ull << (v.x << 3)) + (1ull << (v.y << 3))
                      + (1ull << (v.z << 3)) + (1ull << (v.w << 3));
            }
        }
        mtile[i * TP + 1 + tid] = mrow;
    }
    __syncthreads();

    // 5-wide row-OR window of mask row i (rolling registers, computed once each)
    #define WIN(i, dst) { \
        const unsigned* row_ = &mtile[(i) * TP]; \
        const unsigned L_ = row_[tid], Cm_ = row_[tid + 1], R_ = row_[tid + 2]; \
        const unsigned a_ = __byte_perm(L_, Cm_, 0x5432); \
        const unsigned b2_ = __byte_perm(L_, Cm_, 0x6543); \
        const unsigned c_ = __byte_perm(Cm_, R_, 0x4321); \
        const unsigned d_ = __byte_perm(Cm_, R_, 0x5432); \
        dst = (a_ | b2_) | Cm_ | (c_ | d_); \
    }
    {
        unsigned w0, w1;
        WIN(1, w0); WIN(2, w1);
        #pragma unroll
        for (int rr = 0; rr < 8; rr++) {
            unsigned w2; WIN(rr + 3, w2);
            const unsigned m = w0 | w1 | w2
                             | mtile[rr * TP + 1 + tid]
                             | mtile[(rr + 4) * TP + 1 + tid];
            const unsigned t2 = m & (m - 0x01010101u);  // center bit set -> no borrow
            const unsigned y  = (((t2 & 0x7f7f7f7fu) + 0x7f7f7f7fu) | t2);
            ctile[rr * 256 + tid] |= ((y >> 7) & 0x01010101u) << 3;
            w0 = w1; w1 = w2;
        }
    }
    __syncthreads();   // all mask reads done -> reuse mtile as dice bins

    float* inter_s = (float*)mtile;        // 8*256 bins, own-column only (no races)
    #pragma unroll
    for (int c = 0; c < 8; c++) inter_s[c * 256 + tid] = 0.f;

    // ===== phase 2: fully-unrolled 16-step packed-f32x2 pipeline (no padding) =====
    ull ps2[8];                            // packed probsum accumulators (lo px, hi px)
    #pragma unroll
    for (int c = 0; c < 8; c++) ps2[c] = 0ull;
    float ce_s = 0.f, cb_s = 0.f;          // lg2 units
    const ull L2E2 = pk2(L2EF, L2EF);

    // linear walk: step st covers row r0+(st>>1), x-half (st&1); addr += 2KB/step.
    #pragma unroll
    for (int st = 0; st < 16; st++) {
        // x = v*log2e (packed), exp2 both halves, packed running sum
        float el[8], eh[8];
        ull e2[8];
        ull sa = 0ull, sb = 0ull;
        #pragma unroll
        for (int c = 0; c < 8; c++) {
            const ull x = mul2(nb2[c], L2E2);
            float xl, xh; up2(x, xl, xh);
            el[c] = ex2f_(xl); eh[c] = ex2f_(xh);
            e2[c] = pk2(el[c], eh[c]);
            if (c & 1) sb = add2(sb, e2[c]); else sa = add2(sa, e2[c]);
        }
        if (st + 1 < 16) {                 // prefetch next step (+2KB)
            const float* pn = pb + 512;
            #pragma unroll
            for (int c = 0; c < 8; c++) nb2[c] = __ldcs((const ull*)(pn + c * HW_));
            pb = pn;
        }
        float sl, sh; up2(add2(sa, sb), sl, sh);

        const float invl = rcpf_(sl), invh = rcpf_(sh);
        const ull inv2 = pk2(invl, invh);

        #pragma unroll
        for (int c = 0; c < 8; c++) ps2[c] = fma2_(e2[c], inv2, ps2[c]);

        // u16 index st*256+tid == (row within band)*512 + half*256 + tid
        const unsigned cw = ((const unsigned short*)ctile)[st * 256 + tid];
        const int tl = cw & 7, th = (cw >> 8) & 7;

        float etl = el[0], eth = eh[0];
        #pragma unroll
        for (int c = 1; c < 8; c++) {
            etl = (tl == c) ? el[c] : etl;
            eth = (th == c) ? eh[c] : eth;
        }

        inter_s[tl * 256 + tid] += etl * invl;    // conflict-free: bank = tid % 32
        inter_s[th * 256 + tid] += eth * invh;

        const float cel = lg2f(etl * invl);       // log2 p_t
        const float ceh = lg2f(eth * invh);
        ce_s -= cel + ceh;
        cb_s -= (cw & 8u)     ? cel : 0.f;
        cb_s -= (cw & 0x800u) ? ceh : 0.f;
    }

    float probsum[8], inter[8];
    #pragma unroll
    for (int c = 0; c < 8; c++) {
        float a, z; up2(ps2[c], a, z);
        probsum[c] = a + z;
        inter[c] = inter_s[c * 256 + tid];
    }

    // ============ block reduction -> per-block slots ============
    #pragma unroll
    for (int c = 0; c < 8; c++) { probsum[c] = wredf(probsum[c]); inter[c] = wredf(inter[c]); }
    ce_s = wredf(ce_s);
    cb_s = wredf(cb_s);
    float cntf[8];
    #pragma unroll
    for (int c = 0; c < 8; c++) cntf[c] = wredf((float)(int)((hist >> (c * 8)) & 0xffull));

    const int wid = tid >> 5, lane = tid & 31;
    if (lane == 0) {
        #pragma unroll
        for (int c = 0; c < 8; c++) {
            sred[wid][c]      = probsum[c];
            sred[wid][8 + c]  = inter[c];
            sred[wid][18 + c] = cntf[c];
        }
        sred[wid][16] = ce_s; sred[wid][17] = cb_s;
    }
    __syncthreads();
    if (tid < 26) {
        float s = 0.f;
        #pragma unroll
        for (int w = 0; w < 8; w++) s += sred[w][tid];
        const int i = tid;
        int row;
        if      (i < 8)   row = b * 8 + i;            // probsum
        else if (i < 16)  row = 64 + b * 8 + (i - 8); // inter
        else if (i == 16) row = 128 + b;              // ce (lg2)
        else if (i == 17) row = 136 + b;              // cb (lg2)
        else              row = 144 + b * 8 + (i-18); // cnt
        g_lp[row * NBLK + bid] = s;
    }

    // ============ last block finalizes ============
    __threadfence();
    __syncthreads();
    if (tid == 0) s_ticket = atomicAdd(&g_ctr, 1u);
    __syncthreads();
    if (s_ticket != NBLK - 1) return;

    if (tid < 208) {
        const float4* rp = (const float4*)&g_lp[tid * NBLK];
        float s = 0.f;
        #pragma unroll 4
        for (int x = 0; x < NBLK / 4; x++) {
            const float4 v = rp[x];
            s += (v.x + v.y) + (v.z + v.w);
        }
        S[tid] = s;
    }
    __syncthreads();

    if (tid < 64) {
        float term = (2.f * S[64 + tid] + 1e-6f) / (S[tid] + S[144 + tid] + 1e-6f);
        term = wredf(term);
        if ((tid & 31) == 0) dpart[tid >> 5] = term;
    }
    __syncthreads();
    if (tid == 0) {
        float ce = 0.f, cb = 0.f;
        #pragma unroll
        for (int k = 0; k < 8; k++) { ce += S[128 + k]; cb += S[136 + k]; }
        ce *= LN2F; cb *= LN2F;                          // lg2 -> ln
        const float invN = 1.f / (float)NPIX;
        const float ce_m = ce * invN;
        const float bd   = (ce + 9.f * cb) * invN;       // wmap: 10 on boundary, 1 else
        const float dice = 1.f - (dpart[0] + dpart[1]) * (1.f / 64.f);
        out[0] = 1.f * ce_m + 3.f * dice + 2.f * bd;
        g_ctr = 0;   // reset for next graph replay (deterministic)
    }
}

// ---------------- launch ----------------
extern "C" void kernel_launch(void* const* d_in, const int* in_sizes, int n_in,
                              void* d_out, int out_size) {
    (void)n_in; (void)out_size;
    const float* pred;
    const int*   tgt;
    if (in_sizes[0] == B_ * C_ * HW_) {
        pred = (const float*)d_in[0];
        tgt  = (const int*)d_in[1];
    } else {
        pred = (const float*)d_in[1];
        tgt  = (const int*)d_in[0];
    }
    fused_kernel<<<dim3(GXB, B_), 256>>>(pred, tgt, (float*)d_out);
}

// round 17
// speedup vs baseline: 1.5582x; 1.5020x over previous
#include <cuda_runtime.h>

#define B_   8
#define C_   8
#define H_   512
#define W_   1024
#define HW_  (H_*W_)
#define NPIX (B_*HW_)

#define GXB  74                   // bands per image (6-7 rows each)
#define NBLK (GXB * B_)           // 592 = 4 CTAs x 148 SMs -> exactly one wave
#define TP   258                  // mask tile pitch (1 zero halo u32 each side)
#define LN2F 0.69314718055994531f
#define L2EF 1.4426950408889634f

typedef unsigned long long ull;

// ---------------- device accumulators (no allocations allowed) ----------------
// zero-initialized at load; last block reads then RESETS them each replay.
// 0..63 probsum(b*8+c), 64..127 inter(b*8+c), 128..135 ce(b) [lg2 units],
// 136..143 cb(b) [lg2 units], 144..207 cnt(b*8+c)
__device__ float g_acc[208];
__device__ unsigned int g_ctr = 0;

__device__ __forceinline__ float wredf(float v) {
    #pragma unroll
    for (int o = 16; o; o >>= 1) v += __shfl_xor_sync(0xffffffffu, v, o);
    return v;
}
__device__ __forceinline__ float lg2f(float x) {
    float r; asm("lg2.approx.f32 %0, %1;" : "=f"(r) : "f"(x)); return r;
}
__device__ __forceinline__ float ex2f_(float x) {
    float r; asm("ex2.approx.f32 %0, %1;" : "=f"(r) : "f"(x)); return r;
}
__device__ __forceinline__ float rcpf_(float x) {
    float r; asm("rcp.approx.f32 %0, %1;" : "=f"(r) : "f"(x)); return r;
}
__device__ __forceinline__ ull mul2(ull a, ull b) {
    ull r; asm("mul.rn.f32x2 %0, %1, %2;" : "=l"(r) : "l"(a), "l"(b)); return r;
}
__device__ __forceinline__ ull add2(ull a, ull b) {
    ull r; asm("add.rn.f32x2 %0, %1, %2;" : "=l"(r) : "l"(a), "l"(b)); return r;
}
__device__ __forceinline__ ull fma2_(ull a, ull b, ull c) {
    ull r; asm("fma.rn.f32x2 %0, %1, %2, %3;" : "=l"(r) : "l"(a), "l"(b), "l"(c)); return r;
}
__device__ __forceinline__ ull pk2(float lo, float hi) {
    ull r; asm("mov.b64 %0, {%1, %2};" : "=l"(r) : "f"(lo), "f"(hi)); return r;
}
__device__ __forceinline__ void up2(ull v, float& lo, float& hi) {
    asm("mov.b64 {%0, %1}, %2;" : "=f"(lo), "=f"(hi) : "l"(v));
}

// ---------------- single fused kernel ----------------
__global__ __launch_bounds__(256, 4)
void fused_kernel(const float* __restrict__ pred, const int* __restrict__ tgt,
                  float* __restrict__ out) {
    const int b   = blockIdx.y;
    const int kb  = blockIdx.x;
    const int tid = threadIdx.x;
    const int r0  = (kb * H_) / GXB;
    const int r1  = ((kb + 1) * H_) / GXB;   // rows = r1-r0 in {6,7}

    const float* predb = pred + (size_t)b * (C_ * HW_);
    const int*   tgtb  = tgt  + (size_t)b * HW_;

    __shared__ unsigned mtile[11 * TP];    // one-hot mask rows; reused as dice bins
    __shared__ unsigned wtile[9 * 256];    // 5-wide row-OR windows
    __shared__ unsigned ctile[7 * 256];    // per-px byte: class(3b) | bnd<<3
    __shared__ float    sred[8][26];
    __shared__ float    S[208];
    __shared__ float    dpart[2];
    __shared__ unsigned s_ticket;

    // ---- issue step-0 pred loads FIRST: they age in flight during phase 1 ----
    const float* pb = predb + (size_t)r0 * W_ + tid * 2;
    ull nb2[8];
    #pragma unroll
    for (int c = 0; c < 8; c++) nb2[c] = __ldcs((const ull*)(pb + c * HW_));

    // zero halo columns for all 11 mask rows
    if (tid < 22) mtile[(tid >> 1) * TP + ((tid & 1) ? TP - 1 : 0)] = 0u;

    // ===== phase 1: mask rows r0-2 .. r0+8 (OOB rows = 0 = skipped tap) =====
    ull hist = 0ull;                       // byte-packed class counters (<=28/class)
    #pragma unroll
    for (int i = 0; i < 11; i++) {
        const int g = r0 - 2 + i;
        unsigned mrow = 0u;
        if (g >= 0 && g < H_) {
            const int4 v = *(const int4*)(tgtb + g * W_ + tid * 4);
            const unsigned m0 = 1u << v.x, m1 = 1u << v.y, m2 = 1u << v.z, m3 = 1u << v.w;
            mrow = __byte_perm(__byte_perm(m0, m1, 0x0040),
                               __byte_perm(m2, m3, 0x0040), 0x5410);
            if (i >= 2 && i < 9) {
                ctile[(i - 2) * 256 + tid] =
                    __byte_perm(__byte_perm(v.x, v.y, 0x0040),
                                __byte_perm(v.z, v.w, 0x0040), 0x5410);
                if (g < r1) {              // class histogram off the hot loop
                    hist += (1ull << (v.x << 3)) + (1ull << (v.y << 3))
                          + (1ull << (v.z << 3)) + (1ull << (v.w << 3));
                }
            }
        }
        mtile[i * TP + 1 + tid] = mrow;
    }
    __syncthreads();

    // 5-wide row-OR windows for mask rows 1..9 (each computed once)
    #pragma unroll
    for (int i = 0; i < 9; i++) {
        const unsigned* row = &mtile[(i + 1) * TP];
        const unsigned L = row[tid], Cm = row[tid + 1], R = row[tid + 2];
        const unsigned s0 = __byte_perm(L, Cm, 0x5432);   // offset -2
        const unsigned s1 = __byte_perm(L, Cm, 0x6543);   // offset -1
        const unsigned s3 = __byte_perm(Cm, R, 0x4321);   // offset +1
        const unsigned s4 = __byte_perm(Cm, R, 0x5432);   // offset +2
        wtile[i * 256 + tid] = (s0 | s1) | Cm | (s3 | s4);
    }
    __syncthreads();

    // boundary: OR of 3 row-windows + center taps of rows +-2; >=2 distinct classes
    #pragma unroll
    for (int rr = 0; rr < 7; rr++) {
        const unsigned m = wtile[rr * 256 + tid] | wtile[(rr + 1) * 256 + tid]
                         | wtile[(rr + 2) * 256 + tid]
                         | mtile[rr * TP + 1 + tid]
                         | mtile[(rr + 4) * TP + 1 + tid];
        const unsigned t2 = m & (m - 0x01010101u);   // center bit always set -> no borrow
        const unsigned y  = (((t2 & 0x7f7f7f7fu) + 0x7f7f7f7fu) | t2);
        ctile[rr * 256 + tid] |= ((y >> 7) & 0x01010101u) << 3;
    }
    __syncthreads();   // all mask reads done -> reuse mtile as dice bins

    float* inter_s = (float*)mtile;        // 8*256 bins, own-column only (no races)
    #pragma unroll
    for (int c = 0; c < 8; c++) inter_s[c * 256 + tid] = 0.f;

    // ===== phase 2: fully-unrolled 14-step packed-f32x2 pipeline =====
    ull ps2[8];                            // packed probsum accumulators (lo px, hi px)
    #pragma unroll
    for (int c = 0; c < 8; c++) ps2[c] = 0ull;
    float ce_s = 0.f, cb_s = 0.f;          // lg2 units
    const ull L2E2 = pk2(L2EF, L2EF);
    const int sv = (r1 - r0) * 2;          // valid steps (12 or 14)

    // linear walk: step st covers row r0+(st>>1), x-half (st&1); addr += 2KB/step.
    // 6-row bands' padded steps read the NEXT band's rows (in-image, weight 0).
    #pragma unroll
    for (int st = 0; st < 14; st++) {
        // x = v*log2e (packed), exp2 both halves, packed running sum
        float el[8], eh[8];
        ull e2[8];
        ull sa = 0ull, sb = 0ull;
        #pragma unroll
        for (int c = 0; c < 8; c++) {
            const ull x = mul2(nb2[c], L2E2);
            float xl, xh; up2(x, xl, xh);
            el[c] = ex2f_(xl); eh[c] = ex2f_(xh);
            e2[c] = pk2(el[c], eh[c]);
            if (c & 1) sb = add2(sb, e2[c]); else sa = add2(sa, e2[c]);
        }
        if (st + 1 < 14) {                 // prefetch next step (+2KB)
            const float* pn = pb + 512;
            #pragma unroll
            for (int c = 0; c < 8; c++) nb2[c] = __ldcs((const ull*)(pn + c * HW_));
            pb = pn;
        }
        float sl, sh; up2(add2(sa, sb), sl, sh);

        const bool valid = st < sv;        // uniform per CTA
        const float invl = rcpf_(sl), invh = rcpf_(sh);
        const float invlw = valid ? invl : 0.f;
        const float invhw = valid ? invh : 0.f;
        const ull inv2w = pk2(invlw, invhw);

        #pragma unroll
        for (int c = 0; c < 8; c++) ps2[c] = fma2_(e2[c], inv2w, ps2[c]);

        const unsigned cw = ((const unsigned short*)ctile)[st * 256 + tid];
        const int tl = cw & 7, th = (cw >> 8) & 7;

        float etl = el[0], eth = eh[0];
        #pragma unroll
        for (int c = 1; c < 8; c++) {
            etl = (tl == c) ? el[c] : etl;
            eth = (th == c) ? eh[c] : eth;
        }

        inter_s[tl * 256 + tid] += etl * invlw;   // conflict-free: bank = tid % 32
        inter_s[th * 256 + tid] += eth * invhw;

        // branchless CE: terms zeroed by SEL on padded steps
        const float cel = lg2f(etl * invl);       // log2 p_t
        const float ceh = lg2f(eth * invh);
        ce_s -= valid ? (cel + ceh) : 0.f;
        cb_s -= ((cw & 8u)     && valid) ? cel : 0.f;
        cb_s -= ((cw & 0x800u) && valid) ? ceh : 0.f;
    }

    float probsum[8], inter[8];
    #pragma unroll
    for (int c = 0; c < 8; c++) {
        float a, z; up2(ps2[c], a, z);
        probsum[c] = a + z;
        inter[c] = inter_s[c * 256 + tid];
    }

    // ============ block reduction -> 26 L2 atomics per block ============
    #pragma unroll
    for (int c = 0; c < 8; c++) { probsum[c] = wredf(probsum[c]); inter[c] = wredf(inter[c]); }
    ce_s = wredf(ce_s);
    cb_s = wredf(cb_s);
    float cntf[8];
    #pragma unroll
    for (int c = 0; c < 8; c++) cntf[c] = wredf((float)(int)((hist >> (c * 8)) & 0xffull));

    const int wid = tid >> 5, lane = tid & 31;
    if (lane == 0) {
        #pragma unroll
        for (int c = 0; c < 8; c++) {
            sred[wid][c]      = probsum[c];
            sred[wid][8 + c]  = inter[c];
            sred[wid][18 + c] = cntf[c];
        }
        sred[wid][16] = ce_s; sred[wid][17] = cb_s;
    }
    __syncthreads();
    if (tid < 26) {
        float s = 0.f;
        #pragma unroll
        for (int w = 0; w < 8; w++) s += sred[w][tid];
        const int i = tid;
        int row;
        if      (i < 8)   row = b * 8 + i;            // probsum
        else if (i < 16)  row = 64 + b * 8 + (i - 8); // inter
        else if (i == 16) row = 128 + b;              // ce (lg2)
        else if (i == 17) row = 136 + b;              // cb (lg2)
        else              row = 144 + b * 8 + (i-18); // cnt
        atomicAdd(&g_acc[row], s);                    // REDG-class: ~0.854 cyc/lane
    }

    // ============ last block finalizes (single coalesced 208-float read) ============
    __threadfence();
    __syncthreads();
    if (tid == 0) s_ticket = atomicAdd(&g_ctr, 1u);
    __syncthreads();
    if (s_ticket != NBLK - 1) return;

    if (tid < 208) S[tid] = g_acc[tid];
    __syncthreads();
    if (tid < 208) g_acc[tid] = 0.f;       // reset for next graph replay

    if (tid < 64) {
        float term = (2.f * S[64 + tid] + 1e-6f) / (S[tid] + S[144 + tid] + 1e-6f);
        term = wredf(term);
        if ((tid & 31) == 0) dpart[tid >> 5] = term;
    }
    __syncthreads();
    if (tid == 0) {
        float ce = 0.f, cb = 0.f;
        #pragma unroll
        for (int k = 0; k < 8; k++) { ce += S[128 + k]; cb += S[136 + k]; }
        ce *= LN2F; cb *= LN2F;                          // lg2 -> ln
        const float invN = 1.f / (float)NPIX;
        const float ce_m = ce * invN;
        const float bd   = (ce + 9.f * cb) * invN;       // wmap: 10 on boundary, 1 else
        const float dice = 1.f - (dpart[0] + dpart[1]) * (1.f / 64.f);
        out[0] = 1.f * ce_m + 3.f * dice + 2.f * bd;
        g_ctr = 0;   // reset for next graph replay
    }
}

// ---------------- launch ----------------
extern "C" void kernel_launch(void* const* d_in, const int* in_sizes, int n_in,
                              void* d_out, int out_size) {
    (void)n_in; (void)out_size;
    const float* pred;
    const int*   tgt;
    if (in_sizes[0] == B_ * C_ * HW_) {
        pred = (const float*)d_in[0];
        tgt  = (const int*)d_in[1];
    } else {
        pred = (const float*)d_in[1];
        tgt  = (const int*)d_in[0];
    }
    fused_kernel<<<dim3(GXB, B_), 256>>>(pred, tgt, (float*)d_out);
}